// round 3
// baseline (speedup 1.0000x reference)
#include <cuda_runtime.h>

// Problem constants
#define BB    128   // batch
#define TT    32    // time steps
#define DD    128   // feature dim
#define NSLOT 128   // memory slots
#define BITS  32    // bits per slot
#define HH    4     // heads
#define UU    256   // controller hidden
#define HDW   128   // H*BITS
#define CTLW  256   // D + HD
#define OUTW  384   // D + 2*HD
#define MPITCH 36   // padded pitch for M rows (16B aligned, decent bank behavior)

// Weight pinning in shared memory
#define RC_PIN 128                  // pinned rows of Wc (of 256)
#define RF_PIN 36                   // pinned rows of Wf (of 256)
#define PIN_WC (RC_PIN * UU)        // 32768 floats
#define PIN_WF (RF_PIN * OUTW)      // 13824 floats
#define NPIN   (PIN_WC + PIN_WF)    // 46592 floats

struct SmemLayout {
    float M[NSLOT * MPITCH];   // 4608 floats, memory matrix (pitch 36)
    float ctl[CTLW];           // [x_t | read_input]
    float hctl[UU];            // relu hidden
    float o[OUTW];             // controller output
    float rW[HH * NSLOT];      // read weights (state)
    float wW[HH * NSLOT];      // write weights (state, post-Pt)
    float hisW[HH * NSLOT];    // history weights (state)
    float e[HH * NSLOT];       // softmax logit workspace
    float rv[HDW];             // read head vector (state)
    float minv[NSLOT];         // per-slot inverse norms of M
    float kinv[HH];            // read-key inverse norms
    float kinvw[HH];           // write-key inverse norms
    float beta_s[HH * NSLOT];
    float g_s[HH * NSLOT];
    float Wg_s[HH * NSLOT];
    float er_s[HH * BITS];
    float ad_s[HH * BITS];
    float wpin[NPIN];          // pinned prefix of Wc then Wf
};
// total = 56200 floats = 224800 bytes < 227KB opt-in limit

// warp row-softmax over N=128 with blend: dst = g*softmax(e_row) + (1-g)*dst
__device__ __forceinline__ void softmax_blend_row(const float* __restrict__ e,
                                                  const float* __restrict__ gv,
                                                  float* __restrict__ dst,
                                                  int h, int lane)
{
    float v[4];
#pragma unroll
    for (int i = 0; i < 4; ++i) v[i] = e[h * NSLOT + lane + i * 32];
    float m = fmaxf(fmaxf(v[0], v[1]), fmaxf(v[2], v[3]));
#pragma unroll
    for (int off = 16; off > 0; off >>= 1) m = fmaxf(m, __shfl_xor_sync(0xffffffffu, m, off));
    float sum = 0.f;
#pragma unroll
    for (int i = 0; i < 4; ++i) { v[i] = __expf(v[i] - m); sum += v[i]; }
#pragma unroll
    for (int off = 16; off > 0; off >>= 1) sum += __shfl_xor_sync(0xffffffffu, sum, off);
    float inv = 1.0f / sum;
#pragma unroll
    for (int i = 0; i < 4; ++i) {
        int n = lane + i * 32;
        float gg = gv[h * NSLOT + n];
        dst[h * NSLOT + n] = gg * (v[i] * inv) + (1.f - gg) * dst[h * NSLOT + n];
    }
}

// key-vs-memory cosine logits: e[h,n] = -beta[h,n] * kinv[h] * minv[n] * (key_h . M_n)
__device__ __forceinline__ void sim_logits(SmemLayout* s, const float* __restrict__ keys,
                                           const float* __restrict__ kinvv, int tid)
{
#pragma unroll 1
    for (int p = tid; p < HH * NSLOT; p += 256) {
        int h = p >> 7, n = p & 127;
        const float4* Mr = reinterpret_cast<const float4*>(&s->M[n * MPITCH]);
        const float4* Kr = reinterpret_cast<const float4*>(&keys[h * BITS]);
        float raw = 0.f;
#pragma unroll
        for (int i = 0; i < 8; ++i) {
            float4 mm = Mr[i];
            float4 kk = Kr[i];
            raw += mm.x * kk.x + mm.y * kk.y + mm.z * kk.z + mm.w * kk.w;
        }
        s->e[p] = -s->beta_s[p] * kinvv[h] * s->minv[n] * raw;
    }
}

__global__ __launch_bounds__(256, 1)
void uic_kernel(const float* __restrict__ x, const float* __restrict__ beta,
                const float* __restrict__ g, const float* __restrict__ erase,
                const float* __restrict__ add, const float* __restrict__ Wg,
                const float* __restrict__ M0, const float* __restrict__ read0,
                const float* __restrict__ readW0, const float* __restrict__ writeW0,
                const float* __restrict__ Wc, const float* __restrict__ bc,
                const float* __restrict__ Wf, const float* __restrict__ bf,
                float* __restrict__ out)
{
    extern __shared__ float smem_raw[];
    SmemLayout* s = reinterpret_cast<SmemLayout*>(smem_raw);
    const int b = blockIdx.x;
    const int tid = threadIdx.x;
    const int lane = tid & 31;
    const int warp = tid >> 5;

    // ---------------- init: load per-batch state + pin weights ----------------
    for (int idx = tid; idx < NSLOT * BITS; idx += 256) {
        int n = idx >> 5, d = idx & 31;
        s->M[n * MPITCH + d] = M0[b * NSLOT * BITS + idx];
    }
    for (int idx = tid; idx < HH * NSLOT; idx += 256) {
        s->rW[idx]     = readW0[b * HH * NSLOT + idx];
        s->wW[idx]     = writeW0[b * HH * NSLOT + idx];
        s->hisW[idx]   = 0.f;
        s->beta_s[idx] = beta[idx];
        s->g_s[idx]    = g[idx];
        s->Wg_s[idx]   = Wg[b * HH * NSLOT + idx];
    }
    for (int idx = tid; idx < HDW; idx += 256) {
        s->rv[idx]   = read0[b * HDW + idx];
        s->er_s[idx] = erase[b * HDW + idx];
        s->ad_s[idx] = add[b * HDW + idx];
    }
    for (int idx = tid; idx < PIN_WC; idx += 256) s->wpin[idx] = Wc[idx];
    for (int idx = tid; idx < PIN_WF; idx += 256) s->wpin[PIN_WC + idx] = Wf[idx];
    __syncthreads();

    for (int t = 0; t < TT; ++t) {
        // ---- P0/P1: load x_t; norms of M rows and read key ----
        if (tid < DD) s->ctl[tid] = x[b * TT * DD + t * DD + tid];
        if (tid < NSLOT) {
            const float4* Mr = reinterpret_cast<const float4*>(&s->M[tid * MPITCH]);
            float ss = 0.f;
#pragma unroll
            for (int i = 0; i < 8; ++i) {
                float4 v = Mr[i];
                ss += v.x * v.x + v.y * v.y + v.z * v.z + v.w * v.w;
            }
            s->minv[tid] = rsqrtf(fmaxf(ss, 1e-12f));
        } else if (tid < NSLOT + HH) {
            int h = tid - NSLOT;
            float ss = 0.f;
#pragma unroll
            for (int k = 0; k < BITS; ++k) { float v = s->rv[h * BITS + k]; ss += v * v; }
            s->kinv[h] = rsqrtf(fmaxf(ss, 1e-12f));
        }
        __syncthreads();

        // ---- P2: read addressing ----
        sim_logits(s, s->rv, s->kinv, tid);
        __syncthreads();
        if (warp < HH) softmax_blend_row(s->e, s->g_s, s->rW, warp, lane);
        __syncthreads();

        // ---- P3: read_input[h,d] = sum_n rW[h,n] * M[n,d] ----
        if (tid < HDW) {
            int h = tid >> 5, d = tid & 31;
            const float* rw = &s->rW[h * NSLOT];
            float a0 = 0.f, a1 = 0.f, a2 = 0.f, a3 = 0.f;
#pragma unroll 4
            for (int n = 0; n < NSLOT; n += 4) {
                a0 += rw[n]     * s->M[n * MPITCH + d];
                a1 += rw[n + 1] * s->M[(n + 1) * MPITCH + d];
                a2 += rw[n + 2] * s->M[(n + 2) * MPITCH + d];
                a3 += rw[n + 3] * s->M[(n + 3) * MPITCH + d];
            }
            s->ctl[DD + tid] = a0 + a1 + a2 + a3;
        }
        __syncthreads();

        // ---- P4: hctl = relu(ctl @ Wc + bc), one output per thread ----
        {
            const int u = tid;
            float a0 = 0.f, a1 = 0.f, a2 = 0.f, a3 = 0.f;
            const float* wp = s->wpin;
#pragma unroll 4
            for (int k = 0; k < RC_PIN; k += 4) {
                a0 += s->ctl[k]     * wp[k * UU + u];
                a1 += s->ctl[k + 1] * wp[(k + 1) * UU + u];
                a2 += s->ctl[k + 2] * wp[(k + 2) * UU + u];
                a3 += s->ctl[k + 3] * wp[(k + 3) * UU + u];
            }
#pragma unroll 4
            for (int k = RC_PIN; k < CTLW; k += 4) {
                a0 += s->ctl[k]     * __ldg(&Wc[k * UU + u]);
                a1 += s->ctl[k + 1] * __ldg(&Wc[(k + 1) * UU + u]);
                a2 += s->ctl[k + 2] * __ldg(&Wc[(k + 2) * UU + u]);
                a3 += s->ctl[k + 3] * __ldg(&Wc[(k + 3) * UU + u]);
            }
            s->hctl[u] = fmaxf(a0 + a1 + a2 + a3 + __ldg(&bc[u]), 0.f);
        }
        __syncthreads();

        // ---- P5: o = hctl @ Wf + bf ----
        for (int v = tid; v < OUTW; v += 256) {
            float a0 = 0.f, a1 = 0.f, a2 = 0.f, a3 = 0.f;
            const float* wfp = &s->wpin[PIN_WC];
#pragma unroll 4
            for (int k = 0; k < RF_PIN; k += 4) {
                a0 += s->hctl[k]     * wfp[k * OUTW + v];
                a1 += s->hctl[k + 1] * wfp[(k + 1) * OUTW + v];
                a2 += s->hctl[k + 2] * wfp[(k + 2) * OUTW + v];
                a3 += s->hctl[k + 3] * wfp[(k + 3) * OUTW + v];
            }
#pragma unroll 4
            for (int k = RF_PIN; k < UU; k += 4) {
                a0 += s->hctl[k]     * __ldg(&Wf[k * OUTW + v]);
                a1 += s->hctl[k + 1] * __ldg(&Wf[(k + 1) * OUTW + v]);
                a2 += s->hctl[k + 2] * __ldg(&Wf[(k + 2) * OUTW + v]);
                a3 += s->hctl[k + 3] * __ldg(&Wf[(k + 3) * OUTW + v]);
            }
            s->o[v] = a0 + a1 + a2 + a3 + __ldg(&bf[v]);
        }
        __syncthreads();

        // ---- P6: emit output, stash new read head, write-key norms ----
        if (tid < DD) out[b * TT * DD + t * DD + tid] = s->o[tid];
        else          s->rv[tid - DD] = s->o[tid];           // read_head for next step
        if (tid < HH) {
            float ss = 0.f;
#pragma unroll
            for (int k = 0; k < BITS; ++k) { float v = s->o[CTLW + tid * BITS + k]; ss += v * v; }
            s->kinvw[tid] = rsqrtf(fmaxf(ss, 1e-12f));
        }
        __syncthreads();

        // ---- P7: write addressing (uses OLD M, minv still valid) ----
        sim_logits(s, &s->o[CTLW], s->kinvw, tid);
        __syncthreads();
        if (warp < HH) softmax_blend_row(s->e, s->g_s, s->wW, warp, lane);
        __syncthreads();

        // ---- P8: M update with pre-Pt writeW ----
        for (int idx = tid; idx < NSLOT * BITS; idx += 256) {
            int n = idx >> 5, d = idx & 31;
            float ew = 0.f, aw = 0.f;
#pragma unroll
            for (int h = 0; h < HH; ++h) {
                float w = s->wW[h * NSLOT + n];
                ew += w * s->er_s[h * BITS + d];
                aw += w * s->ad_s[h * BITS + d];
            }
            float mv = s->M[n * MPITCH + d];
            s->M[n * MPITCH + d] = mv * (1.f - ew) + aw;
        }
        __syncthreads();

        // ---- P9: Pt = softmax(Wg*hisW); writeW *= Pt; hisW += writeW ----
        if (warp < HH) {
            int h = warp;
            float v[4];
#pragma unroll
            for (int i = 0; i < 4; ++i) {
                int n = lane + i * 32;
                v[i] = s->Wg_s[h * NSLOT + n] * s->hisW[h * NSLOT + n];
            }
            float m = fmaxf(fmaxf(v[0], v[1]), fmaxf(v[2], v[3]));
#pragma unroll
            for (int off = 16; off > 0; off >>= 1) m = fmaxf(m, __shfl_xor_sync(0xffffffffu, m, off));
            float sum = 0.f;
#pragma unroll
            for (int i = 0; i < 4; ++i) { v[i] = __expf(v[i] - m); sum += v[i]; }
#pragma unroll
            for (int off = 16; off > 0; off >>= 1) sum += __shfl_xor_sync(0xffffffffu, sum, off);
            float inv = 1.0f / sum;
#pragma unroll
            for (int i = 0; i < 4; ++i) {
                int n = lane + i * 32;
                float wnew = s->wW[h * NSLOT + n] * (v[i] * inv);
                s->wW[h * NSLOT + n] = wnew;
                s->hisW[h * NSLOT + n] += wnew;
            }
        }
        __syncthreads();
    }
}

extern "C" void kernel_launch(void* const* d_in, const int* in_sizes, int n_in,
                              void* d_out, int out_size)
{
    const float* x       = (const float*)d_in[0];
    const float* beta    = (const float*)d_in[1];
    const float* g       = (const float*)d_in[2];
    const float* erase   = (const float*)d_in[3];
    const float* add     = (const float*)d_in[4];
    const float* Wg      = (const float*)d_in[5];
    const float* M0      = (const float*)d_in[6];
    const float* read0   = (const float*)d_in[7];
    const float* readW0  = (const float*)d_in[8];
    const float* writeW0 = (const float*)d_in[9];
    // d_in[10] = S0   (dead: S never influences the output)
    const float* Wc      = (const float*)d_in[11];
    const float* bc      = (const float*)d_in[12];
    const float* Wf      = (const float*)d_in[13];
    const float* bf      = (const float*)d_in[14];
    // d_in[15..17] = Wi, Ui, b_gru (dead: GRU-over-slots only feeds S)

    (void)in_sizes; (void)n_in; (void)out_size;

    cudaFuncSetAttribute(uic_kernel, cudaFuncAttributeMaxDynamicSharedMemorySize,
                         (int)sizeof(SmemLayout));
    uic_kernel<<<BB, 256, sizeof(SmemLayout)>>>(x, beta, g, erase, add, Wg,
                                                M0, read0, readW0, writeW0,
                                                Wc, bc, Wf, bf, (float*)d_out);
}

// round 4
// speedup vs baseline: 1.7461x; 1.7461x over previous
#include <cuda_runtime.h>

// Problem constants
#define BB    128   // batch
#define TT    32    // time steps
#define DD    128   // feature dim
#define NSLOT 128   // memory slots
#define BITS  32    // bits per slot
#define HH    4     // heads
#define UU    256   // controller hidden
#define HDW   128   // H*BITS
#define CTLW  256   // D + HD
#define OUTW  384   // D + 2*HD
#define MPITCH 36   // padded pitch for M rows (16B aligned)
#define THREADS 512

// Weight pinning in shared memory
#define RC_PIN 128                  // pinned rows of Wc (of 256)
#define RF_PIN 32                   // pinned rows of Wf (of 256)
#define PIN_WC (RC_PIN * UU)        // 32768 floats
#define PIN_WF (RF_PIN * OUTW)     // 12288 floats

struct SmemLayout {
    float M[NSLOT * MPITCH];   // 4608
    float ctl[CTLW];
    float hctl[UU];
    float o[OUTW];
    float rW[HH * NSLOT];
    float wW[HH * NSLOT];
    float hisW[HH * NSLOT];
    float e[HH * NSLOT];
    float rv[HDW];
    float minv[NSLOT];
    float kinv[HH];
    float kinvw[HH];
    float beta_s[HH * NSLOT];
    float g_s[HH * NSLOT];
    float Wg_s[HH * NSLOT];
    float er_s[HH * BITS];
    float ad_s[HH * BITS];
    float bc_s[UU];
    float bf_s[OUTW];
    float red[2048];           // split-k reduction scratch (8 KB)
    float wpinC[PIN_WC];       // Wc rows [0,128)
    float wpinF[PIN_WF];       // Wf rows [0,32)
};
// 57352 floats = 229,408 bytes < 227 KB opt-in (232,448 B)

__device__ __forceinline__ void softmax_blend_row(const float* __restrict__ e,
                                                  const float* __restrict__ gv,
                                                  float* __restrict__ dst,
                                                  int h, int lane)
{
    float v[4];
#pragma unroll
    for (int i = 0; i < 4; ++i) v[i] = e[h * NSLOT + lane + i * 32];
    float m = fmaxf(fmaxf(v[0], v[1]), fmaxf(v[2], v[3]));
#pragma unroll
    for (int off = 16; off > 0; off >>= 1) m = fmaxf(m, __shfl_xor_sync(0xffffffffu, m, off));
    float sum = 0.f;
#pragma unroll
    for (int i = 0; i < 4; ++i) { v[i] = __expf(v[i] - m); sum += v[i]; }
#pragma unroll
    for (int off = 16; off > 0; off >>= 1) sum += __shfl_xor_sync(0xffffffffu, sum, off);
    float inv = 1.0f / sum;
#pragma unroll
    for (int i = 0; i < 4; ++i) {
        int n = lane + i * 32;
        float gg = gv[h * NSLOT + n];
        dst[h * NSLOT + n] = gg * (v[i] * inv) + (1.f - gg) * dst[h * NSLOT + n];
    }
}

// one logit per thread (512 threads == H*N)
__device__ __forceinline__ void sim_logits(SmemLayout* s, const float* __restrict__ keys,
                                           const float* __restrict__ kinvv, int tid)
{
    int h = tid >> 7, n = tid & 127;
    const float4* Mr = reinterpret_cast<const float4*>(&s->M[n * MPITCH]);
    const float4* Kr = reinterpret_cast<const float4*>(&keys[h * BITS]);
    float raw = 0.f;
#pragma unroll
    for (int i = 0; i < 8; ++i) {
        float4 mm = Mr[i];
        float4 kk = Kr[i];
        raw += mm.x * kk.x + mm.y * kk.y + mm.z * kk.z + mm.w * kk.w;
    }
    s->e[tid] = -s->beta_s[tid] * kinvv[h] * s->minv[n] * raw;
}

__global__ __launch_bounds__(THREADS, 1)
void uic_kernel(const float* __restrict__ x, const float* __restrict__ beta,
                const float* __restrict__ g, const float* __restrict__ erase,
                const float* __restrict__ add, const float* __restrict__ Wg,
                const float* __restrict__ M0, const float* __restrict__ read0,
                const float* __restrict__ readW0, const float* __restrict__ writeW0,
                const float* __restrict__ Wc, const float* __restrict__ bc,
                const float* __restrict__ Wf, const float* __restrict__ bf,
                float* __restrict__ out)
{
    extern __shared__ float smem_raw[];
    SmemLayout* s = reinterpret_cast<SmemLayout*>(smem_raw);
    const int b = blockIdx.x;
    const int tid = threadIdx.x;
    const int lane = tid & 31;
    const int warp = tid >> 5;

    // ---------------- init ----------------
    for (int idx = tid; idx < NSLOT * BITS; idx += THREADS) {
        int n = idx >> 5, d = idx & 31;
        s->M[n * MPITCH + d] = M0[b * NSLOT * BITS + idx];
    }
    for (int idx = tid; idx < HH * NSLOT; idx += THREADS) {
        s->rW[idx]     = readW0[b * HH * NSLOT + idx];
        s->wW[idx]     = writeW0[b * HH * NSLOT + idx];
        s->hisW[idx]   = 0.f;
        s->beta_s[idx] = beta[idx];
        s->g_s[idx]    = g[idx];
        s->Wg_s[idx]   = Wg[b * HH * NSLOT + idx];
    }
    for (int idx = tid; idx < HDW; idx += THREADS) {
        s->rv[idx]   = read0[b * HDW + idx];
        s->er_s[idx] = erase[b * HDW + idx];
        s->ad_s[idx] = add[b * HDW + idx];
    }
    for (int idx = tid; idx < UU; idx += THREADS)   s->bc_s[idx] = bc[idx];
    for (int idx = tid; idx < OUTW; idx += THREADS) s->bf_s[idx] = bf[idx];
    for (int idx = tid; idx < PIN_WC; idx += THREADS) s->wpinC[idx] = Wc[idx];
    for (int idx = tid; idx < PIN_WF; idx += THREADS) s->wpinF[idx] = Wf[idx];
    __syncthreads();

    for (int t = 0; t < TT; ++t) {
        // ---- P0: x_t load, M-row norms, read-key norms (disjoint warps) ----
        if (tid < DD) {
            s->ctl[tid] = x[b * TT * DD + t * DD + tid];
        } else if (tid < 2 * NSLOT) {
            int n = tid - NSLOT;
            const float4* Mr = reinterpret_cast<const float4*>(&s->M[n * MPITCH]);
            float ss = 0.f;
#pragma unroll
            for (int i = 0; i < 8; ++i) {
                float4 v = Mr[i];
                ss += v.x * v.x + v.y * v.y + v.z * v.z + v.w * v.w;
            }
            s->minv[n] = rsqrtf(fmaxf(ss, 1e-12f));
        } else if (tid < 2 * NSLOT + HH) {
            int h = tid - 2 * NSLOT;
            float ss = 0.f;
#pragma unroll
            for (int k = 0; k < BITS; ++k) { float v = s->rv[h * BITS + k]; ss += v * v; }
            s->kinv[h] = rsqrtf(fmaxf(ss, 1e-12f));
        }
        __syncthreads();

        // ---- P2: read addressing ----
        sim_logits(s, s->rv, s->kinv, tid);
        __syncthreads();
        if (warp < HH) softmax_blend_row(s->e, s->g_s, s->rW, warp, lane);
        __syncthreads();

        // ---- P3: read_input[h,d] = sum_n rW[h,n]*M[n,d], 4-way split-k ----
        {
            int grp = tid >> 7;            // 0..3
            int idx = tid & 127;
            int h = idx >> 5, d = idx & 31;
            const float* rw = &s->rW[h * NSLOT];
            float a = 0.f;
            int n0 = grp * 32;
#pragma unroll 8
            for (int n = n0; n < n0 + 32; ++n) a += rw[n] * s->M[n * MPITCH + d];
            s->red[grp * 128 + idx] = a;
        }
        __syncthreads();
        if (tid < HDW) {
            s->ctl[DD + tid] = s->red[tid] + s->red[128 + tid]
                             + s->red[256 + tid] + s->red[384 + tid];
        }
        __syncthreads();

        // ---- P4: hctl = relu(ctl@Wc+bc), float4 outputs, 8-way split-k ----
        {
            int grp = tid >> 6;            // 0..7
            int l   = tid & 63;
            int u4  = l * 4;
            float4 acc = make_float4(0.f, 0.f, 0.f, 0.f);
            if (grp < 4) {                 // pinned rows from smem
                int k0 = grp * 32;
#pragma unroll 8
                for (int k = k0; k < k0 + 32; ++k) {
                    float4 w = *reinterpret_cast<const float4*>(&s->wpinC[k * UU + u4]);
                    float c = s->ctl[k];
                    acc.x += c * w.x; acc.y += c * w.y; acc.z += c * w.z; acc.w += c * w.w;
                }
            } else {                       // streamed rows from L2 (LDG.128)
                int k0 = RC_PIN + (grp - 4) * 32;
#pragma unroll 8
                for (int k = k0; k < k0 + 32; ++k) {
                    float4 w = __ldg(reinterpret_cast<const float4*>(&Wc[k * UU + u4]));
                    float c = s->ctl[k];
                    acc.x += c * w.x; acc.y += c * w.y; acc.z += c * w.z; acc.w += c * w.w;
                }
            }
            *reinterpret_cast<float4*>(&s->red[grp * UU + u4]) = acc;
        }
        __syncthreads();
        if (tid < UU) {
            float a = s->bc_s[tid];
#pragma unroll
            for (int grp = 0; grp < 8; ++grp) a += s->red[grp * UU + tid];
            s->hctl[tid] = fmaxf(a, 0.f);
        }
        __syncthreads();

        // ---- P5: o = hctl@Wf+bf, float4 outputs, 4-way split-k ----
        if (tid < 384) {
            int grp = tid / 96;            // 0..3
            int l   = tid - grp * 96;
            int v4  = l * 4;
            float4 acc = make_float4(0.f, 0.f, 0.f, 0.f);
            int kp0 = grp * 8;             // 8 pinned rows
#pragma unroll
            for (int k = kp0; k < kp0 + 8; ++k) {
                float4 w = *reinterpret_cast<const float4*>(&s->wpinF[k * OUTW + v4]);
                float c = s->hctl[k];
                acc.x += c * w.x; acc.y += c * w.y; acc.z += c * w.z; acc.w += c * w.w;
            }
            int ks0 = RF_PIN + grp * 56;   // 56 streamed rows
#pragma unroll 8
            for (int k = ks0; k < ks0 + 56; ++k) {
                float4 w = __ldg(reinterpret_cast<const float4*>(&Wf[k * OUTW + v4]));
                float c = s->hctl[k];
                acc.x += c * w.x; acc.y += c * w.y; acc.z += c * w.z; acc.w += c * w.w;
            }
            *reinterpret_cast<float4*>(&s->red[grp * OUTW + v4]) = acc;
        }
        __syncthreads();
        if (tid < OUTW) {
            s->o[tid] = s->bf_s[tid] + s->red[tid] + s->red[OUTW + tid]
                      + s->red[2 * OUTW + tid] + s->red[3 * OUTW + tid];
        }
        __syncthreads();

        // ---- P6: emit output, stash read head, write-key norms ----
        if (tid < DD)        out[b * TT * DD + t * DD + tid] = s->o[tid];
        else if (tid < CTLW) s->rv[tid - DD] = s->o[tid];
        if (tid >= CTLW && tid < CTLW + HH) {
            int h = tid - CTLW;
            float ss = 0.f;
#pragma unroll
            for (int k = 0; k < BITS; ++k) { float v = s->o[CTLW + h * BITS + k]; ss += v * v; }
            s->kinvw[h] = rsqrtf(fmaxf(ss, 1e-12f));
        }
        __syncthreads();

        // ---- P7: write addressing (old M; minv still valid) ----
        sim_logits(s, &s->o[CTLW], s->kinvw, tid);
        __syncthreads();
        if (warp < HH) softmax_blend_row(s->e, s->g_s, s->wW, warp, lane);
        __syncthreads();

        // ---- P8: M update with pre-Pt writeW ----
        for (int idx = tid; idx < NSLOT * BITS; idx += THREADS) {
            int n = idx >> 5, d = idx & 31;
            float ew = 0.f, aw = 0.f;
#pragma unroll
            for (int h = 0; h < HH; ++h) {
                float w = s->wW[h * NSLOT + n];
                ew += w * s->er_s[h * BITS + d];
                aw += w * s->ad_s[h * BITS + d];
            }
            float mv = s->M[n * MPITCH + d];
            s->M[n * MPITCH + d] = mv * (1.f - ew) + aw;
        }
        __syncthreads();

        // ---- P9: Pt = softmax(Wg*hisW); writeW *= Pt; hisW += writeW ----
        if (warp < HH) {
            int h = warp;
            float v[4];
#pragma unroll
            for (int i = 0; i < 4; ++i) {
                int n = lane + i * 32;
                v[i] = s->Wg_s[h * NSLOT + n] * s->hisW[h * NSLOT + n];
            }
            float m = fmaxf(fmaxf(v[0], v[1]), fmaxf(v[2], v[3]));
#pragma unroll
            for (int off = 16; off > 0; off >>= 1) m = fmaxf(m, __shfl_xor_sync(0xffffffffu, m, off));
            float sum = 0.f;
#pragma unroll
            for (int i = 0; i < 4; ++i) { v[i] = __expf(v[i] - m); sum += v[i]; }
#pragma unroll
            for (int off = 16; off > 0; off >>= 1) sum += __shfl_xor_sync(0xffffffffu, sum, off);
            float inv = 1.0f / sum;
#pragma unroll
            for (int i = 0; i < 4; ++i) {
                int n = lane + i * 32;
                float wnew = s->wW[h * NSLOT + n] * (v[i] * inv);
                s->wW[h * NSLOT + n] = wnew;
                s->hisW[h * NSLOT + n] += wnew;
            }
        }
        __syncthreads();
    }
}

extern "C" void kernel_launch(void* const* d_in, const int* in_sizes, int n_in,
                              void* d_out, int out_size)
{
    const float* x       = (const float*)d_in[0];
    const float* beta    = (const float*)d_in[1];
    const float* g       = (const float*)d_in[2];
    const float* erase   = (const float*)d_in[3];
    const float* add     = (const float*)d_in[4];
    const float* Wg      = (const float*)d_in[5];
    const float* M0      = (const float*)d_in[6];
    const float* read0   = (const float*)d_in[7];
    const float* readW0  = (const float*)d_in[8];
    const float* writeW0 = (const float*)d_in[9];
    // d_in[10] = S0   (dead: S never influences the output)
    const float* Wc      = (const float*)d_in[11];
    const float* bc      = (const float*)d_in[12];
    const float* Wf      = (const float*)d_in[13];
    const float* bf      = (const float*)d_in[14];
    // d_in[15..17] = Wi, Ui, b_gru (dead)

    (void)in_sizes; (void)n_in; (void)out_size;

    cudaFuncSetAttribute(uic_kernel, cudaFuncAttributeMaxDynamicSharedMemorySize,
                         (int)sizeof(SmemLayout));
    uic_kernel<<<BB, THREADS, sizeof(SmemLayout)>>>(x, beta, g, erase, add, Wg,
                                                    M0, read0, readW0, writeW0,
                                                    Wc, bc, Wf, bf, (float*)d_out);
}

// round 5
// speedup vs baseline: 1.7864x; 1.0231x over previous
#include <cuda_runtime.h>

// Problem constants
#define BB    128
#define TT    32
#define DD    128
#define NSLOT 128
#define BITS  32
#define HH    4
#define UU    256
#define HDW   128
#define CTLW  256
#define OUTW  384
#define MPITCH 36
#define THREADS 768

// Weight pinning in shared memory
#define RC_PIN 128
#define RF_PIN 32
#define PIN_WC (RC_PIN * UU)    // 32768 floats
#define PIN_WF (RF_PIN * OUTW)  // 12288 floats
#define REDN   3072             // split-k scratch; also aliases e[512]

struct SmemLayout {
    float M[NSLOT * MPITCH];   // 4608
    float ctl[CTLW];
    float hctl[UU];
    float o[OUTW];
    float rW[HH * NSLOT];
    float wW[HH * NSLOT];
    float hisW[HH * NSLOT];
    float rv[HDW];
    float minv[NSLOT];
    float kinv[HH];
    float kinvw[HH];
    float beta_s[HH * NSLOT];
    float g_s[HH * NSLOT];
    float Wg_s[HH * NSLOT];
    float er_s[HH * BITS];
    float ad_s[HH * BITS];
    float bc_s[UU];
    float bf_s[OUTW];
    float red[REDN];           // logits e[] alias red[0..511]
    float wpinC[PIN_WC];
    float wpinF[PIN_WF];
};
// 57,864 floats = 231,456 bytes <= 232,448 B opt-in

__device__ __forceinline__ void softmax_blend_row(const float* __restrict__ e,
                                                  const float* __restrict__ gv,
                                                  float* __restrict__ dst,
                                                  int h, int lane)
{
    float v[4];
#pragma unroll
    for (int i = 0; i < 4; ++i) v[i] = e[h * NSLOT + lane + i * 32];
    float m = fmaxf(fmaxf(v[0], v[1]), fmaxf(v[2], v[3]));
#pragma unroll
    for (int off = 16; off > 0; off >>= 1) m = fmaxf(m, __shfl_xor_sync(0xffffffffu, m, off));
    float sum = 0.f;
#pragma unroll
    for (int i = 0; i < 4; ++i) { v[i] = __expf(v[i] - m); sum += v[i]; }
#pragma unroll
    for (int off = 16; off > 0; off >>= 1) sum += __shfl_xor_sync(0xffffffffu, sum, off);
    float inv = 1.0f / sum;
#pragma unroll
    for (int i = 0; i < 4; ++i) {
        int n = lane + i * 32;
        float gg = gv[h * NSLOT + n];
        dst[h * NSLOT + n] = gg * (v[i] * inv) + (1.f - gg) * dst[h * NSLOT + n];
    }
}

// one logit per thread for tid<512 (writes into red[] used as e[])
__device__ __forceinline__ void sim_logits(SmemLayout* s, const float* __restrict__ keys,
                                           const float* __restrict__ kinvv, int tid)
{
    if (tid < HH * NSLOT) {
        int h = tid >> 7, n = tid & 127;
        const float4* Mr = reinterpret_cast<const float4*>(&s->M[n * MPITCH]);
        const float4* Kr = reinterpret_cast<const float4*>(&keys[h * BITS]);
        float raw = 0.f;
#pragma unroll
        for (int i = 0; i < 8; ++i) {
            float4 mm = Mr[i];
            float4 kk = Kr[i];
            raw += mm.x * kk.x + mm.y * kk.y + mm.z * kk.z + mm.w * kk.w;
        }
        s->red[tid] = -s->beta_s[tid] * kinvv[h] * s->minv[n] * raw;
    }
}

__global__ __launch_bounds__(THREADS, 1)
void uic_kernel(const float* __restrict__ x, const float* __restrict__ beta,
                const float* __restrict__ g, const float* __restrict__ erase,
                const float* __restrict__ add, const float* __restrict__ Wg,
                const float* __restrict__ M0, const float* __restrict__ read0,
                const float* __restrict__ readW0, const float* __restrict__ writeW0,
                const float* __restrict__ Wc, const float* __restrict__ bc,
                const float* __restrict__ Wf, const float* __restrict__ bf,
                float* __restrict__ out)
{
    extern __shared__ float smem_raw[];
    SmemLayout* s = reinterpret_cast<SmemLayout*>(smem_raw);
    const int b = blockIdx.x;
    const int tid = threadIdx.x;
    const int lane = tid & 31;
    const int warp = tid >> 5;

    // ---------------- init ----------------
    for (int idx = tid; idx < NSLOT * BITS; idx += THREADS) {
        int n = idx >> 5, d = idx & 31;
        s->M[n * MPITCH + d] = M0[b * NSLOT * BITS + idx];
    }
    for (int idx = tid; idx < HH * NSLOT; idx += THREADS) {
        s->rW[idx]     = readW0[b * HH * NSLOT + idx];
        s->wW[idx]     = writeW0[b * HH * NSLOT + idx];
        s->hisW[idx]   = 0.f;
        s->beta_s[idx] = beta[idx];
        s->g_s[idx]    = g[idx];
        s->Wg_s[idx]   = Wg[b * HH * NSLOT + idx];
    }
    for (int idx = tid; idx < HDW; idx += THREADS) {
        s->rv[idx]   = read0[b * HDW + idx];
        s->er_s[idx] = erase[b * HDW + idx];
        s->ad_s[idx] = add[b * HDW + idx];
    }
    for (int idx = tid; idx < UU; idx += THREADS)   s->bc_s[idx] = bc[idx];
    for (int idx = tid; idx < OUTW; idx += THREADS) s->bf_s[idx] = bf[idx];
    for (int idx = tid; idx < PIN_WC; idx += THREADS) s->wpinC[idx] = Wc[idx];
    for (int idx = tid; idx < PIN_WF; idx += THREADS) s->wpinF[idx] = Wf[idx];
    __syncthreads();

    // ---------------- prologue (t=0 prep: x, minv, kinv) ----------------
    if (tid < DD) {
        s->ctl[tid] = x[b * TT * DD + tid];
    } else if (tid < 2 * NSLOT) {
        int n = tid - NSLOT;
        const float4* Mr = reinterpret_cast<const float4*>(&s->M[n * MPITCH]);
        float ss = 0.f;
#pragma unroll
        for (int i = 0; i < 8; ++i) {
            float4 v = Mr[i];
            ss += v.x * v.x + v.y * v.y + v.z * v.z + v.w * v.w;
        }
        s->minv[n] = rsqrtf(fmaxf(ss, 1e-12f));
    } else if (tid >= 384 && tid < 384 + HH) {
        int h = tid - 384;
        float ss = 0.f;
#pragma unroll
        for (int k = 0; k < BITS; ++k) { float v = s->rv[h * BITS + k]; ss += v * v; }
        s->kinv[h] = rsqrtf(fmaxf(ss, 1e-12f));
    }
    __syncthreads();

    static const int P3S[7] = {0, 22, 44, 65, 86, 107, 128};

    for (int t = 0; t < TT; ++t) {
        // ---- P2: read addressing logits ----
        sim_logits(s, s->rv, s->kinv, tid);
        __syncthreads();
        if (warp < HH) softmax_blend_row(s->red, s->g_s, s->rW, warp, lane);
        __syncthreads();

        // ---- P3: read_input[h,d] = sum_n rW[h,n]*M[n,d], 6-way split-k ----
        {
            int grp = tid / 128;           // 0..5
            int idx = tid & 127;
            int h = idx >> 5, d = idx & 31;
            const float* rw = &s->rW[h * NSLOT];
            float a = 0.f;
            int n0 = P3S[grp], n1 = P3S[grp + 1];
#pragma unroll 4
            for (int n = n0; n < n1; ++n) a += rw[n] * s->M[n * MPITCH + d];
            s->red[grp * 128 + idx] = a;
        }
        __syncthreads();
        if (tid < HDW) {
            float a = 0.f;
#pragma unroll
            for (int grp = 0; grp < 6; ++grp) a += s->red[grp * 128 + tid];
            s->ctl[DD + tid] = a;
        }
        __syncthreads();

        // ---- P4: hctl partials, 12 groups x 64 thr (4 pinned, 8 streamed) ----
        {
            int grp = tid >> 6;            // 0..11
            int u4  = (tid & 63) * 4;
            float4 acc = make_float4(0.f, 0.f, 0.f, 0.f);
            if (grp < 4) {                 // pinned rows: 32 each, from smem
                int k0 = grp * 32;
#pragma unroll 8
                for (int k = k0; k < k0 + 32; ++k) {
                    float4 w = *reinterpret_cast<const float4*>(&s->wpinC[k * UU + u4]);
                    float c = s->ctl[k];
                    acc.x += c * w.x; acc.y += c * w.y; acc.z += c * w.z; acc.w += c * w.w;
                }
            } else {                       // streamed rows: 16 each, LDG.128
                int k0 = RC_PIN + (grp - 4) * 16;
#pragma unroll 8
                for (int k = k0; k < k0 + 16; ++k) {
                    float4 w = __ldg(reinterpret_cast<const float4*>(&Wc[k * UU + u4]));
                    float c = s->ctl[k];
                    acc.x += c * w.x; acc.y += c * w.y; acc.z += c * w.z; acc.w += c * w.w;
                }
            }
            *reinterpret_cast<float4*>(&s->red[grp * UU + u4]) = acc;
        }
        __syncthreads();
        if (tid < UU) {
            float a = s->bc_s[tid];
#pragma unroll
            for (int grp = 0; grp < 12; ++grp) a += s->red[grp * UU + tid];
            s->hctl[tid] = fmaxf(a, 0.f);
        }
        __syncthreads();

        // ---- P5: o partials, 8 groups x 96 thr (grp0 pinned 32, grp1-7 streamed 32) ----
        {
            int grp = tid / 96;            // 0..7
            int v4  = (tid - grp * 96) * 4;
            float4 acc = make_float4(0.f, 0.f, 0.f, 0.f);
            if (grp == 0) {
#pragma unroll 8
                for (int k = 0; k < RF_PIN; ++k) {
                    float4 w = *reinterpret_cast<const float4*>(&s->wpinF[k * OUTW + v4]);
                    float c = s->hctl[k];
                    acc.x += c * w.x; acc.y += c * w.y; acc.z += c * w.z; acc.w += c * w.w;
                }
            } else {
                int k0 = RF_PIN + (grp - 1) * 32;
#pragma unroll 8
                for (int k = k0; k < k0 + 32; ++k) {
                    float4 w = __ldg(reinterpret_cast<const float4*>(&Wf[k * OUTW + v4]));
                    float c = s->hctl[k];
                    acc.x += c * w.x; acc.y += c * w.y; acc.z += c * w.z; acc.w += c * w.w;
                }
            }
            *reinterpret_cast<float4*>(&s->red[grp * OUTW + v4]) = acc;
        }
        __syncthreads();

        // ---- P5-reduce fused with P6 (emit out / rv / o-keys / kinvw) ----
        if (tid < OUTW) {
            float a = s->bf_s[tid];
#pragma unroll
            for (int grp = 0; grp < 8; ++grp) a += s->red[grp * OUTW + tid];
            if (tid < DD) {
                out[b * TT * DD + t * DD + tid] = a;
            } else if (tid < CTLW) {
                s->rv[tid - DD] = a;                   // next step's read key
            } else {
                s->o[tid] = a;                          // write-head keys for P7
                // warp 8+h holds head h's 32 values: in-warp norm reduce
                float ss = a * a;
#pragma unroll
                for (int off = 16; off > 0; off >>= 1) ss += __shfl_xor_sync(0xffffffffu, ss, off);
                if (lane == 0) s->kinvw[warp - 8] = rsqrtf(fmaxf(ss, 1e-12f));
            }
        }
        __syncthreads();

        // ---- P7: write addressing (old M; minv still valid) ----
        sim_logits(s, &s->o[CTLW], s->kinvw, tid);
        __syncthreads();
        if (warp < HH) softmax_blend_row(s->red, s->g_s, s->wW, warp, lane);
        __syncthreads();

        // ---- P8: M update with pre-Pt writeW ----
        for (int idx = tid; idx < NSLOT * BITS; idx += THREADS) {
            int n = idx >> 5, d = idx & 31;
            float ew = 0.f, aw = 0.f;
#pragma unroll
            for (int h = 0; h < HH; ++h) {
                float w = s->wW[h * NSLOT + n];
                ew += w * s->er_s[h * BITS + d];
                aw += w * s->ad_s[h * BITS + d];
            }
            float mv = s->M[n * MPITCH + d];
            s->M[n * MPITCH + d] = mv * (1.f - ew) + aw;
        }
        __syncthreads();

        // ---- PF: fused P9 (warps 0-3) + next-step prep (warps 4-12) ----
        if (warp < HH) {
            // Pt = softmax(Wg*hisW); writeW *= Pt; hisW += writeW
            int h = warp;
            float v[4];
#pragma unroll
            for (int i = 0; i < 4; ++i) {
                int n = lane + i * 32;
                v[i] = s->Wg_s[h * NSLOT + n] * s->hisW[h * NSLOT + n];
            }
            float m = fmaxf(fmaxf(v[0], v[1]), fmaxf(v[2], v[3]));
#pragma unroll
            for (int off = 16; off > 0; off >>= 1) m = fmaxf(m, __shfl_xor_sync(0xffffffffu, m, off));
            float sum = 0.f;
#pragma unroll
            for (int i = 0; i < 4; ++i) { v[i] = __expf(v[i] - m); sum += v[i]; }
#pragma unroll
            for (int off = 16; off > 0; off >>= 1) sum += __shfl_xor_sync(0xffffffffu, sum, off);
            float inv = 1.0f / sum;
#pragma unroll
            for (int i = 0; i < 4; ++i) {
                int n = lane + i * 32;
                float wnew = s->wW[h * NSLOT + n] * (v[i] * inv);
                s->wW[h * NSLOT + n] = wnew;
                s->hisW[h * NSLOT + n] += wnew;
            }
        } else if (tid < 2 * NSLOT) {
            // M-row norms for next step (M finalized at P8)
            int n = tid - NSLOT;
            const float4* Mr = reinterpret_cast<const float4*>(&s->M[n * MPITCH]);
            float ss = 0.f;
#pragma unroll
            for (int i = 0; i < 8; ++i) {
                float4 v = Mr[i];
                ss += v.x * v.x + v.y * v.y + v.z * v.z + v.w * v.w;
            }
            s->minv[n] = rsqrtf(fmaxf(ss, 1e-12f));
        } else if (tid < 384) {
            // prefetch x for next step
            if (t + 1 < TT) s->ctl[tid - 256] = x[b * TT * DD + (t + 1) * DD + (tid - 256)];
        } else if (tid < 384 + HH) {
            // read-key norm for next step (rv written in P5-reduce)
            int h = tid - 384;
            float ss = 0.f;
#pragma unroll
            for (int k = 0; k < BITS; ++k) { float v = s->rv[h * BITS + k]; ss += v * v; }
            s->kinv[h] = rsqrtf(fmaxf(ss, 1e-12f));
        }
        __syncthreads();
    }
}

extern "C" void kernel_launch(void* const* d_in, const int* in_sizes, int n_in,
                              void* d_out, int out_size)
{
    const float* x       = (const float*)d_in[0];
    const float* beta    = (const float*)d_in[1];
    const float* g       = (const float*)d_in[2];
    const float* erase   = (const float*)d_in[3];
    const float* add     = (const float*)d_in[4];
    const float* Wg      = (const float*)d_in[5];
    const float* M0      = (const float*)d_in[6];
    const float* read0   = (const float*)d_in[7];
    const float* readW0  = (const float*)d_in[8];
    const float* writeW0 = (const float*)d_in[9];
    // d_in[10] = S0   (dead)
    const float* Wc      = (const float*)d_in[11];
    const float* bc      = (const float*)d_in[12];
    const float* Wf      = (const float*)d_in[13];
    const float* bf      = (const float*)d_in[14];
    // d_in[15..17] = Wi, Ui, b_gru (dead)

    (void)in_sizes; (void)n_in; (void)out_size;

    cudaFuncSetAttribute(uic_kernel, cudaFuncAttributeMaxDynamicSharedMemorySize,
                         (int)sizeof(SmemLayout));
    uic_kernel<<<BB, THREADS, sizeof(SmemLayout)>>>(x, beta, g, erase, add, Wg,
                                                    M0, read0, readW0, writeW0,
                                                    Wc, bc, Wf, bf, (float*)d_out);
}